// round 8
// baseline (speedup 1.0000x reference)
#include <cuda_runtime.h>
#include <math.h>

// ---------------- problem constants ----------------
#define BB   2
#define CIN  2048
#define MID  64
#define DQ   8
#define NC   19
#define HH   96
#define WW   96
#define NPIX (HH*WW)            // 9216
#define FEAT (BB*MID*NPIX)      // 1179648
#define BN_EPS 1e-5f

// ---------------- device scratch (no allocations allowed) ----------------
__device__ float g_y1[FEAT];            // conv_in output (bn+relu), later reused as conv_out output
__device__ float g_z [FEAT];            // cls1 x-part partial sums (raw)
__device__ float g_fa[FEAT];            // cca ping
__device__ float g_fb[FEAT];            // cca pong
__device__ float g_q [BB*DQ*NPIX];
__device__ float g_k [BB*DQ*NPIX];
__device__ float g_v [FEAT];
__device__ float g_att[BB*NPIX*192];
__device__ float g_oH[FEAT];
__device__ float g_small[BB*NC*NPIX];   // pre-upsample 19-ch logits

// ---------------- packed f32x2 helpers (sm_103a FFMA2 path) ----------------
__device__ __forceinline__ unsigned long long dup2(float v) {
    unsigned long long r;
    unsigned int u = __float_as_uint(v);
    asm("mov.b64 %0, {%1, %1};" : "=l"(r) : "r"(u));
    return r;
}
__device__ __forceinline__ void fma2(unsigned long long& acc,
                                     unsigned long long a, unsigned long long b) {
    asm("fma.rn.f32x2 %0, %1, %2, %0;" : "+l"(acc) : "l"(a), "l"(b));
}
__device__ __forceinline__ void unpack2(unsigned long long p, float& lo, float& hi) {
    unsigned int ulo, uhi;
    asm("mov.b64 {%0, %1}, %2;" : "=r"(ulo), "=r"(uhi) : "l"(p));
    lo = __uint_as_float(ulo); hi = __uint_as_float(uhi);
}

// =====================================================================
// K1: fused conv_in (oc 0..63, bn+relu) + conv_cls1 x-slice (oc 64..127, raw)
// tile: 128 oc x (32x4 px), 256 threads, per-thread 8oc x 8px via FFMA2:
// oc-pairs packed in f32x2 (weight pair = one LDS.64), input dup'd per tap.
// Arithmetic identical to scalar fmaf version (each half is fma.rn.f32).
// =====================================================================
__global__ __launch_bounds__(256, 1) void conv_big_kernel(
    const float* __restrict__ x, const float* __restrict__ w_in,
    const float* __restrict__ w_cls1,
    const float* __restrict__ bng, const float* __restrict__ bnb,
    const float* __restrict__ bnm, const float* __restrict__ bnv,
    float* __restrict__ y1, float* __restrict__ z)
{
    const int tx0 = blockIdx.x * 32, ty0 = blockIdx.y * 4, b = blockIdx.z;
    __shared__ float in_s[8][6][34];
    __shared__ float w_s[72][130];     // [ic*9+tap][oc], pad 130 -> 8B-aligned rows for LDS.64
    const int tid = threadIdx.x;
    const int og = tid >> 4;           // 0..15 : oc group (8 oc) — broadcast weight reads in warp
    const int pg = tid & 15;           // 0..15 : px group (8 px)
    const int lx = (pg & 3) * 8;
    const int ly = pg >> 2;

    unsigned long long acc2[4][8];     // [oc-pair][px], lo half = even oc
#pragma unroll
    for (int i = 0; i < 4; i++)
#pragma unroll
        for (int j = 0; j < 8; j++) acc2[i][j] = 0ull;

    for (int ic0 = 0; ic0 < CIN; ic0 += 8) {
        // ---- load input tile (8 ch x 6 x 34, halo = 1) ----
        for (int i = tid; i < 8*6*34; i += 256) {
            int ic = i / 204, r = i % 204;
            int ry = r / 34, rx = r % 34;
            int gy = ty0 + ry - 1, gx = tx0 + rx - 1;
            float val = 0.f;
            if ((unsigned)gy < HH && (unsigned)gx < WW)
                val = x[((b*CIN + ic0 + ic)*HH + gy)*WW + gx];
            in_s[ic][ry][rx] = val;
        }
        // ---- load weights: 128 oc x 8 ic x 9 taps ----
        for (int e = tid; e < 128*72; e += 256) {
            int oc = e / 72, r = e % 72;           // r = ic*9 + tap (contiguous in gmem)
            int ic = r / 9, tap = r % 9;
            float val = (oc < 64)
                ? w_in  [( oc      *CIN  + ic0 + ic)*9 + tap]
                : w_cls1[((oc - 64)*2112 + ic0 + ic)*9 + tap];
            w_s[r][oc] = val;
        }
        __syncthreads();
#pragma unroll
        for (int ic = 0; ic < 8; ic++) {
#pragma unroll
            for (int dy = 0; dy < 3; dy++) {
                unsigned long long rdup[10];
#pragma unroll
                for (int t = 0; t < 10; t++) rdup[t] = dup2(in_s[ic][ly + dy][lx + t]);
#pragma unroll
                for (int dx = 0; dx < 3; dx++) {
                    const unsigned long long* wrow =
                        reinterpret_cast<const unsigned long long*>(&w_s[ic*9 + dy*3 + dx][og*8]);
                    unsigned long long wp[4];
#pragma unroll
                    for (int i = 0; i < 4; i++) wp[i] = wrow[i];
#pragma unroll
                    for (int i = 0; i < 4; i++)
#pragma unroll
                        for (int j = 0; j < 8; j++)
                            fma2(acc2[i][j], wp[i], rdup[j + dx]);
                }
            }
        }
        __syncthreads();
    }

    const int gy = ty0 + ly;
#pragma unroll
    for (int i = 0; i < 4; i++) {
        int oc0 = og*8 + 2*i;                 // pair (oc0, oc0+1); same side of 64 split
        float vlo[8], vhi[8];
#pragma unroll
        for (int j = 0; j < 8; j++) unpack2(acc2[i][j], vlo[j], vhi[j]);
        if (oc0 < 64) {
            float sc0 = bng[oc0]   * rsqrtf(bnv[oc0]   + BN_EPS);
            float bs0 = bnb[oc0]   - bnm[oc0]*sc0;
            float sc1 = bng[oc0+1] * rsqrtf(bnv[oc0+1] + BN_EPS);
            float bs1 = bnb[oc0+1] - bnm[oc0+1]*sc1;
            float* o0 = y1 + ((b*MID + oc0  )*HH + gy)*WW + tx0 + lx;
            float* o1 = y1 + ((b*MID + oc0+1)*HH + gy)*WW + tx0 + lx;
#pragma unroll
            for (int j = 0; j < 8; j++) {
                o0[j] = fmaxf(vlo[j]*sc0 + bs0, 0.f);
                o1[j] = fmaxf(vhi[j]*sc1 + bs1, 0.f);
            }
        } else {
            float* o0 = z + ((b*MID + oc0-64)*HH + gy)*WW + tx0 + lx;
            float* o1 = z + ((b*MID + oc0-63)*HH + gy)*WW + tx0 + lx;
#pragma unroll
            for (int j = 0; j < 8; j++) { o0[j] = vlo[j]; o1[j] = vhi[j]; }
        }
    }
}

// =====================================================================
// conv_small: 64ch -> 64ch 3x3, optional add (cls1 partial), bn, optional relu
// tile: 64 oc x (32x4 px), 256 threads, per-thread 8oc x 4px
// =====================================================================
__global__ __launch_bounds__(256, 1) void conv_small_kernel(
    const float* __restrict__ in, const float* __restrict__ w, int w_oc_stride,
    const float* __restrict__ addp,
    const float* __restrict__ bng, const float* __restrict__ bnb,
    const float* __restrict__ bnm, const float* __restrict__ bnv,
    int relu, float* __restrict__ out)
{
    const int tx0 = blockIdx.x * 32, ty0 = blockIdx.y * 4, b = blockIdx.z;
    __shared__ float in_s[8][6][34];
    __shared__ float w_s[72][65];
    const int tid = threadIdx.x;
    const int og = tid >> 5;          // 0..7  : oc group (8 oc) — per-warp constant
    const int pg = tid & 31;          // 0..31 : px group (4 px)
    const int lx = (pg & 7) * 4;
    const int ly = pg >> 3;

    float acc[8][4];
#pragma unroll
    for (int i = 0; i < 8; i++)
#pragma unroll
        for (int j = 0; j < 4; j++) acc[i][j] = 0.f;

    for (int ic0 = 0; ic0 < MID; ic0 += 8) {
        for (int i = tid; i < 8*6*34; i += 256) {
            int ic = i / 204, r = i % 204;
            int ry = r / 34, rx = r % 34;
            int gy = ty0 + ry - 1, gx = tx0 + rx - 1;
            float val = 0.f;
            if ((unsigned)gy < HH && (unsigned)gx < WW)
                val = in[((b*MID + ic0 + ic)*HH + gy)*WW + gx];
            in_s[ic][ry][rx] = val;
        }
        for (int e = tid; e < 64*72; e += 256) {
            int oc = e / 72, r = e % 72;
            int ic = r / 9, tap = r % 9;
            w_s[r][oc] = w[oc*w_oc_stride + (ic0 + ic)*9 + tap];
        }
        __syncthreads();
#pragma unroll
        for (int ic = 0; ic < 8; ic++) {
#pragma unroll
            for (int dy = 0; dy < 3; dy++) {
                float rin[6];
#pragma unroll
                for (int t = 0; t < 6; t++) rin[t] = in_s[ic][ly + dy][lx + t];
#pragma unroll
                for (int dx = 0; dx < 3; dx++) {
                    float wr[8];
#pragma unroll
                    for (int i = 0; i < 8; i++) wr[i] = w_s[ic*9 + dy*3 + dx][og*8 + i];
#pragma unroll
                    for (int i = 0; i < 8; i++)
#pragma unroll
                        for (int j = 0; j < 4; j++)
                            acc[i][j] = fmaf(wr[i], rin[j + dx], acc[i][j]);
                }
            }
        }
        __syncthreads();
    }

    const int gy = ty0 + ly;
#pragma unroll
    for (int i = 0; i < 8; i++) {
        int oc = og*8 + i;
        float sc = bng[oc] * rsqrtf(bnv[oc] + BN_EPS);
        float bs = bnb[oc] - bnm[oc]*sc;
#pragma unroll
        for (int j = 0; j < 4; j++) {
            int idx = ((b*MID + oc)*HH + gy)*WW + tx0 + lx + j;
            float val = acc[i][j];
            if (addp) val += addp[idx];
            val = val*sc + bs;
            if (relu) val = fmaxf(val, 0.f);
            out[idx] = val;
        }
    }
}

// =====================================================================
// CCA kernels
// =====================================================================
__global__ __launch_bounds__(128) void proj_kernel(
    const float* __restrict__ in, const float* __restrict__ wq,
    const float* __restrict__ wk, const float* __restrict__ wv,
    float* __restrict__ q, float* __restrict__ k, float* __restrict__ v)
{
    __shared__ float swq[DQ*MID], swk[DQ*MID], swv[MID*MID];
    const int tid = threadIdx.x;
    for (int i = tid; i < DQ*MID; i += 128) { swq[i] = wq[i]; swk[i] = wk[i]; }
    for (int i = tid; i < MID*MID; i += 128) swv[i] = wv[i];
    __syncthreads();

    const int px = blockIdx.x*128 + tid;   // 0..18431
    const int b = px / NPIX, hw = px % NPIX;
    float aq[DQ], ak[DQ], av[MID];
#pragma unroll
    for (int d = 0; d < DQ; d++) { aq[d] = 0.f; ak[d] = 0.f; }
#pragma unroll
    for (int d = 0; d < MID; d++) av[d] = 0.f;

    for (int c = 0; c < MID; c++) {
        float xv = in[(b*MID + c)*NPIX + hw];
#pragma unroll
        for (int d = 0; d < DQ; d++) { aq[d] += swq[d*MID + c]*xv; ak[d] += swk[d*MID + c]*xv; }
#pragma unroll
        for (int d = 0; d < MID; d++) av[d] += swv[d*MID + c]*xv;
    }
#pragma unroll
    for (int d = 0; d < DQ; d++) {
        q[(b*DQ + d)*NPIX + hw] = aq[d];
        k[(b*DQ + d)*NPIX + hw] = ak[d];
    }
#pragma unroll
    for (int d = 0; d < MID; d++) v[(b*MID + d)*NPIX + hw] = av[d];
}

__global__ __launch_bounds__(128) void energyH_kernel(
    const float* __restrict__ q, const float* __restrict__ k, float* __restrict__ att)
{
    const int b = blockIdx.x / WW, w = blockIdx.x % WW;
    __shared__ float qs[DQ][HH], ks[DQ][HH];
    const int tid = threadIdx.x;
    for (int i = tid; i < DQ*HH; i += 128) {
        int d = i / HH, h = i % HH;
        qs[d][h] = q[((b*DQ + d)*HH + h)*WW + w];
        ks[d][h] = k[((b*DQ + d)*HH + h)*WW + w];
    }
    __syncthreads();
    for (int i = tid; i < HH*HH; i += 128) {
        int h = i / HH, kk = i % HH;
        float e = 0.f;
#pragma unroll
        for (int d = 0; d < DQ; d++) e += qs[d][h]*ks[d][kk];
        att[((size_t)(b*HH + h)*WW + w)*192 + kk] = (kk == h) ? -INFINITY : e;
    }
}

__global__ __launch_bounds__(128) void energyW_kernel(
    const float* __restrict__ q, const float* __restrict__ k, float* __restrict__ att)
{
    const int b = blockIdx.x / HH, h = blockIdx.x % HH;
    __shared__ float qs[DQ][WW], ks[DQ][WW];
    const int tid = threadIdx.x;
    for (int i = tid; i < DQ*WW; i += 128) {
        int d = i / WW, w = i % WW;
        qs[d][w] = q[((b*DQ + d)*HH + h)*WW + w];
        ks[d][w] = k[((b*DQ + d)*HH + h)*WW + w];
    }
    __syncthreads();
    for (int i = tid; i < WW*WW; i += 128) {
        int w = i / WW, kk = i % WW;
        float e = 0.f;
#pragma unroll
        for (int d = 0; d < DQ; d++) e += qs[d][w]*ks[d][kk];
        att[((size_t)(b*HH + h)*WW + w)*192 + 96 + kk] = e;
    }
}

__global__ __launch_bounds__(256) void softmax_kernel(float* __restrict__ att)
{
    const int warp = threadIdx.x >> 5, lane = threadIdx.x & 31;
    const int px = blockIdx.x*8 + warp;    // < 18432
    float* p = att + (size_t)px*192;
    float vv[6];
#pragma unroll
    for (int i = 0; i < 6; i++) vv[i] = p[lane + 32*i];
    float mx = vv[0];
#pragma unroll
    for (int i = 1; i < 6; i++) mx = fmaxf(mx, vv[i]);
#pragma unroll
    for (int off = 16; off; off >>= 1) mx = fmaxf(mx, __shfl_xor_sync(0xffffffffu, mx, off));
    float s = 0.f;
#pragma unroll
    for (int i = 0; i < 6; i++) { vv[i] = expf(vv[i] - mx); s += vv[i]; }
#pragma unroll
    for (int off = 16; off; off >>= 1) s += __shfl_xor_sync(0xffffffffu, s, off);
    float inv = 1.f / s;
#pragma unroll
    for (int i = 0; i < 6; i++) p[lane + 32*i] = vv[i]*inv;
}

// oH[b,c,h,w] = sum_k aH[b,h,w,k] * v[b,c,k,w]   (one block per (b,w) column)
__global__ __launch_bounds__(256) void aggH_kernel(
    const float* __restrict__ att, const float* __restrict__ v, float* __restrict__ oH)
{
    const int b = blockIdx.x / WW, w = blockIdx.x % WW;
    __shared__ float vs[MID][97];
    __shared__ float as[HH][33];
    const int tid = threadIdx.x;
    for (int i = tid; i < MID*HH; i += 256) {
        int c = i / HH, kk = i % HH;
        vs[c][kk] = v[((b*MID + c)*HH + kk)*WW + w];
    }
    const int hbase = tid >> 4;        // 0..15
    const int cg = (tid & 15) * 4;     // 0..60
    float acc[4][6];
#pragma unroll
    for (int a = 0; a < 4; a++)
#pragma unroll
        for (int t = 0; t < 6; t++) acc[a][t] = 0.f;

    for (int k0 = 0; k0 < HH; k0 += 32) {
        __syncthreads();
        for (int i = tid; i < HH*32; i += 256) {
            int h = i >> 5, kk = i & 31;
            as[h][kk] = att[((size_t)(b*HH + h)*WW + w)*192 + k0 + kk];
        }
        __syncthreads();
#pragma unroll
        for (int kk = 0; kk < 32; kk++) {
            float ah[6], vl[4];
#pragma unroll
            for (int t = 0; t < 6; t++) ah[t] = as[hbase + 16*t][kk];
#pragma unroll
            for (int a = 0; a < 4; a++) vl[a] = vs[cg + a][k0 + kk];
#pragma unroll
            for (int a = 0; a < 4; a++)
#pragma unroll
                for (int t = 0; t < 6; t++) acc[a][t] = fmaf(vl[a], ah[t], acc[a][t]);
        }
    }
#pragma unroll
    for (int a = 0; a < 4; a++)
#pragma unroll
        for (int t = 0; t < 6; t++)
            oH[((b*MID + cg + a)*HH + hbase + 16*t)*WW + w] = acc[a][t];
}

// oW + finalize: out = gamma*(oH+oW) + x_in   (one block per (b,h) row)
__global__ __launch_bounds__(256) void aggW_kernel(
    const float* __restrict__ att, const float* __restrict__ v,
    const float* __restrict__ oH, const float* __restrict__ xin,
    const float* __restrict__ gamma, float* __restrict__ out)
{
    const int b = blockIdx.x / HH, h = blockIdx.x % HH;
    __shared__ float vs[MID][97];
    __shared__ float as[WW][33];
    const int tid = threadIdx.x;
    for (int i = tid; i < MID*WW; i += 256) {
        int c = i / WW, kk = i % WW;
        vs[c][kk] = v[((b*MID + c)*HH + h)*WW + kk];
    }
    const int wbase = tid >> 4;
    const int cg = (tid & 15) * 4;
    float acc[4][6];
#pragma unroll
    for (int a = 0; a < 4; a++)
#pragma unroll
        for (int t = 0; t < 6; t++) acc[a][t] = 0.f;

    for (int k0 = 0; k0 < WW; k0 += 32) {
        __syncthreads();
        for (int i = tid; i < WW*32; i += 256) {
            int w = i >> 5, kk = i & 31;
            as[w][kk] = att[((size_t)(b*HH + h)*WW + w)*192 + 96 + k0 + kk];
        }
        __syncthreads();
#pragma unroll
        for (int kk = 0; kk < 32; kk++) {
            float aw[6], vl[4];
#pragma unroll
            for (int t = 0; t < 6; t++) aw[t] = as[wbase + 16*t][kk];
#pragma unroll
            for (int a = 0; a < 4; a++) vl[a] = vs[cg + a][k0 + kk];
#pragma unroll
            for (int a = 0; a < 4; a++)
#pragma unroll
                for (int t = 0; t < 6; t++) acc[a][t] = fmaf(vl[a], aw[t], acc[a][t]);
        }
    }
    const float gm = gamma[0];
#pragma unroll
    for (int a = 0; a < 4; a++)
#pragma unroll
        for (int t = 0; t < 6; t++) {
            int idx = ((b*MID + cg + a)*HH + h)*WW + wbase + 16*t;
            out[idx] = gm*(oH[idx] + acc[a][t]) + xin[idx];
        }
}

// =====================================================================
// cls2 (1x1 conv 64->19) at 96x96 — commuted ahead of upsample
// =====================================================================
__global__ __launch_bounds__(256) void cls2_kernel(
    const float* __restrict__ t, const float* __restrict__ w2, float* __restrict__ sm)
{
    __shared__ float sw[NC*MID];
    const int tid = threadIdx.x;
    for (int i = tid; i < NC*MID; i += 256) sw[i] = w2[i];
    __syncthreads();
    const int px = blockIdx.x*256 + tid;     // < 18432
    const int b = px / NPIX, hw = px % NPIX;
    float acc[NC];
#pragma unroll
    for (int n = 0; n < NC; n++) acc[n] = 0.f;
    for (int c = 0; c < MID; c++) {
        float xv = t[(b*MID + c)*NPIX + hw];
#pragma unroll
        for (int n = 0; n < NC; n++) acc[n] += sw[n*MID + c]*xv;
    }
#pragma unroll
    for (int n = 0; n < NC; n++) sm[(b*NC + n)*NPIX + hw] = acc[n];
}

// =====================================================================
// bilinear upsample align_corners 96 -> 768 (matches reference op order)
// =====================================================================
__global__ __launch_bounds__(256) void upsample_kernel(
    const float* __restrict__ sm, float* __restrict__ out)
{
    const int idx = blockIdx.x*256 + threadIdx.x;   // < 2*19*768*768
    const int x  = idx % 768;
    const int y  = (idx / 768) % 768;
    const int bc = idx / (768*768);                 // b*19 + c
    const float s = (float)(95.0 / 767.0);
    float py = (float)y * s, px = (float)x * s;
    int ly = (int)floorf(py), lx = (int)floorf(px);
    int hy = min(ly + 1, 95), hx = min(lx + 1, 95);
    float wy = py - (float)ly, wx = px - (float)lx;
    const float* p = sm + (size_t)bc * NPIX;
    float a = p[ly*96 + lx]*(1.f - wy) + p[hy*96 + lx]*wy;
    float b = p[ly*96 + hx]*(1.f - wy) + p[hy*96 + hx]*wy;
    out[idx] = a*(1.f - wx) + b*wx;
}

// =====================================================================
// launch
// =====================================================================
extern "C" void kernel_launch(void* const* d_in, const int* in_sizes, int n_in,
                              void* d_out, int out_size)
{
    const float* x      = (const float*)d_in[0];
    const float* w_in   = (const float*)d_in[1];
    const float* bin_g  = (const float*)d_in[2];
    const float* bin_b  = (const float*)d_in[3];
    const float* bin_m  = (const float*)d_in[4];
    const float* bin_v  = (const float*)d_in[5];
    const float* wq     = (const float*)d_in[6];
    const float* wk     = (const float*)d_in[7];
    const float* wv     = (const float*)d_in[8];
    const float* gamma  = (const float*)d_in[9];
    const float* w_out  = (const float*)d_in[10];
    const float* bo_g   = (const float*)d_in[11];
    const float* bo_b   = (const float*)d_in[12];
    const float* bo_m   = (const float*)d_in[13];
    const float* bo_v   = (const float*)d_in[14];
    const float* w_cls1 = (const float*)d_in[15];
    const float* bc_g   = (const float*)d_in[16];
    const float* bc_b   = (const float*)d_in[17];
    const float* bc_m   = (const float*)d_in[18];
    const float* bc_v   = (const float*)d_in[19];
    const float* w_cls2 = (const float*)d_in[20];

    float *y1, *z, *fa, *fb, *q, *k, *v, *att, *oH, *sm;
    cudaGetSymbolAddress((void**)&y1, g_y1);
    cudaGetSymbolAddress((void**)&z,  g_z);
    cudaGetSymbolAddress((void**)&fa, g_fa);
    cudaGetSymbolAddress((void**)&fb, g_fb);
    cudaGetSymbolAddress((void**)&q,  g_q);
    cudaGetSymbolAddress((void**)&k,  g_k);
    cudaGetSymbolAddress((void**)&v,  g_v);
    cudaGetSymbolAddress((void**)&att, g_att);
    cudaGetSymbolAddress((void**)&oH, g_oH);
    cudaGetSymbolAddress((void**)&sm, g_small);

    dim3 cgrid(3, 24, BB);

    // Stage 1: fused conv_in (bn+relu) + cls1 x-slice partials (single pass over x)
    conv_big_kernel<<<cgrid, 256>>>(x, w_in, w_cls1,
                                    bin_g, bin_b, bin_m, bin_v, y1, z);

    // Stage 2: 2x criss-cross attention (r0: y1->fa, r1: fa->fb; final in fb)
    const float* cca_in = y1;
    float* cca_out = fa;
    for (int r = 0; r < 2; r++) {
        proj_kernel   <<<BB*NPIX/128, 128>>>(cca_in, wq, wk, wv, q, k, v);
        energyH_kernel<<<BB*WW, 128>>>(q, k, att);
        energyW_kernel<<<BB*HH, 128>>>(q, k, att);
        softmax_kernel<<<BB*NPIX/8, 256>>>(att);
        aggH_kernel   <<<BB*WW, 256>>>(att, v, oH);
        aggW_kernel   <<<BB*HH, 256>>>(att, v, oH, cca_in, gamma, cca_out);
        cca_in = cca_out;
        cca_out = fb;
    }

    // Stage 3: conv_out (bn+relu) — reuse y1 as output buffer
    conv_small_kernel<<<cgrid, 256>>>(fb, w_out, 64*9, (const float*)0,
                                      bo_g, bo_b, bo_m, bo_v, 1, y1);

    // Stage 4: cls1 out-slice conv + stashed x-part + bn_cls (no relu) -> fa
    conv_small_kernel<<<cgrid, 256>>>(y1, w_cls1 + 2048*9, 2112*9, z,
                                      bc_g, bc_b, bc_m, bc_v, 0, fa);

    // Stage 5: 1x1 conv 64->19 at 96x96 (commuted with upsample)
    cls2_kernel<<<BB*NPIX/256, 256>>>(fa, w_cls2, sm);

    // Stage 6: bilinear x8 upsample of 19-ch logits -> final output
    upsample_kernel<<<(BB*NC*768*768)/256, 256>>>(sm, (float*)d_out);
}

// round 12
// speedup vs baseline: 2.5866x; 2.5866x over previous
#include <cuda_runtime.h>
#include <cuda_bf16.h>
#include <math.h>

// ---------------- problem constants ----------------
#define BB   2
#define CIN  2048
#define MID  64
#define DQ   8
#define NC   19
#define HH   96
#define WW   96
#define NPIX (HH*WW)            // 9216
#define FEAT (BB*MID*NPIX)      // 1179648
#define BN_EPS 1e-5f

#define NCHUNK 128              // CIN/16
#define WPREP_ELEMS (NCHUNK*9*128*16)   // 2359296

// ---------------- device scratch (no allocations allowed) ----------------
__device__ float g_y1[FEAT];
__device__ float g_z [FEAT];
__device__ float g_fa[FEAT];
__device__ float g_fb[FEAT];
__device__ float g_q [BB*DQ*NPIX];
__device__ float g_k [BB*DQ*NPIX];
__device__ float g_v [FEAT];
__device__ float g_att[BB*NPIX*192];
__device__ float g_oH[FEAT];
__device__ float g_small[BB*NC*NPIX];
__device__ __nv_bfloat16 g_wh[WPREP_ELEMS];   // weights hi, [chunk][tap][oc(128)][lic(16)]
__device__ __nv_bfloat16 g_wl[WPREP_ELEMS];   // weights lo (residual)

// ---------------- mma.sync m16n8k16 bf16 ----------------
__device__ __forceinline__ void mma16816(float* d,
    unsigned a0, unsigned a1, unsigned a2, unsigned a3,
    unsigned b0, unsigned b1)
{
    asm volatile(
        "mma.sync.aligned.m16n8k16.row.col.f32.bf16.bf16.f32 "
        "{%0,%1,%2,%3}, {%4,%5,%6,%7}, {%8,%9}, {%0,%1,%2,%3};\n"
        : "+f"(d[0]), "+f"(d[1]), "+f"(d[2]), "+f"(d[3])
        : "r"(a0), "r"(a1), "r"(a2), "r"(a3), "r"(b0), "r"(b1));
}

// =====================================================================
// weight prep: reorder w_in (oc 0..63) + w_cls1 x-slice (oc 64..127)
// into [chunk][tap][oc][lic] bf16 hi/lo
// =====================================================================
__global__ __launch_bounds__(256) void weight_prep_kernel(
    const float* __restrict__ w_in, const float* __restrict__ w_cls1,
    __nv_bfloat16* __restrict__ WH, __nv_bfloat16* __restrict__ WL)
{
    int idx = blockIdx.x * 256 + threadIdx.x;      // < WPREP_ELEMS
    int lic = idx & 15;
    int r   = idx >> 4;
    int oc  = r & 127;
    int r2  = r >> 7;
    int tap = r2 % 9;
    int chunk = r2 / 9;
    int ic = chunk * 16 + lic;
    float v = (oc < 64) ? w_in[(oc * CIN + ic) * 9 + tap]
                        : w_cls1[((oc - 64) * 2112 + ic) * 9 + tap];
    __nv_bfloat16 h = __float2bfloat16_rn(v);
    WH[idx] = h;
    WL[idx] = __float2bfloat16_rn(v - __bfloat162float(h));
}

// =====================================================================
// conv_big via mma.sync bf16 3-term split.
// CTA tile: 128 oc x (32x4 = 128 px). 256 thr = 8 warps.
// warp = (oc-pair ob 0..3, px-half ph 0..1): 2 oc-tiles x 8 px-tiles.
// Per 16-ic chunk: PV[y 0..5][x 0..33][16 ic] bf16 hi/lo (halo tile, no im2col
// duplication: one mma k-step == one tap), wA[tap][oc][16 lic] hi/lo.
// =====================================================================
#define SMEM_DYN (2*(6*34*16) + 2*(9*128*16)) * 2   // bytes: PV h+l, wA h+l

__global__ __launch_bounds__(256, 1) void conv_big_mma(
    const float* __restrict__ x,
    const __nv_bfloat16* __restrict__ WH, const __nv_bfloat16* __restrict__ WL,
    const float* __restrict__ bng, const float* __restrict__ bnb,
    const float* __restrict__ bnm, const float* __restrict__ bnv,
    float* __restrict__ y1, float* __restrict__ z)
{
    extern __shared__ char dsm[];
    __nv_bfloat16* PVh = (__nv_bfloat16*)dsm;            // [6][34][16]
    __nv_bfloat16* PVl = PVh + 6*34*16;
    __nv_bfloat16* wAh = PVl + 6*34*16;                  // [9][128][16]
    __nv_bfloat16* wAl = wAh + 9*128*16;

    const int tx0 = blockIdx.x * 32, ty0 = blockIdx.y * 4, b = blockIdx.z;
    const int tid  = threadIdx.x;
    const int lane = tid & 31;
    const int g = lane >> 2;          // 0..7
    const int t = lane & 3;           // 0..3
    const int warp = tid >> 5;        // 0..7
    const int ob = warp >> 1;         // oc-pair 0..3 -> oc tiles at ob*32, ob*32+16
    const int ph = warp & 1;          // px half: tiles ph*8 .. ph*8+7

    float d0[8][4], d1[8][4];
#pragma unroll
    for (int j = 0; j < 8; j++)
#pragma unroll
        for (int c = 0; c < 4; c++) { d0[j][c] = 0.f; d1[j][c] = 0.f; }

    for (int chunk = 0; chunk < NCHUNK; chunk++) {
        __syncthreads();   // guard overwrite of previous chunk's tiles
        // ---- PV fill: x tile (16 ic x 6 x 34 halo), bf16 hi/lo ----
        for (int i = tid; i < 16*204; i += 256) {
            int lic = i / 204, pos = i % 204;
            int y = pos / 34, xx = pos % 34;
            int gy = ty0 + y - 1, gx = tx0 + xx - 1;
            float v = 0.f;
            if ((unsigned)gy < HH && (unsigned)gx < WW)
                v = x[((b*CIN + chunk*16 + lic)*HH + gy)*WW + gx];
            __nv_bfloat16 h = __float2bfloat16_rn(v);
            PVh[(y*34 + xx)*16 + lic] = h;
            PVl[(y*34 + xx)*16 + lic] = __float2bfloat16_rn(v - __bfloat162float(h));
        }
        // ---- wA copy: contiguous 36864B each from prepped arrays ----
        {
            const uint4* sH = (const uint4*)(WH + (size_t)chunk * (9*128*16));
            const uint4* sL = (const uint4*)(WL + (size_t)chunk * (9*128*16));
            uint4* dH = (uint4*)wAh;
            uint4* dL = (uint4*)wAl;
            for (int i = tid; i < 2304; i += 256) { dH[i] = sH[i]; dL[i] = sL[i]; }
        }
        __syncthreads();
        // ---- compute ----
#pragma unroll
        for (int tap = 0; tap < 9; tap++) {
            const int dy = tap / 3, dx = tap % 3;
            const unsigned* pA0h = (const unsigned*)(wAh + (tap*128 + ob*32     )*16);
            const unsigned* pA0l = (const unsigned*)(wAl + (tap*128 + ob*32     )*16);
            const unsigned* pA1h = (const unsigned*)(wAh + (tap*128 + ob*32 + 16)*16);
            const unsigned* pA1l = (const unsigned*)(wAl + (tap*128 + ob*32 + 16)*16);
            unsigned a0h[4], a0l[4], a1h[4], a1l[4];
            a0h[0]=pA0h[g*8+t];     a0h[1]=pA0h[(8+g)*8+t];
            a0h[2]=pA0h[g*8+t+4];   a0h[3]=pA0h[(8+g)*8+t+4];
            a0l[0]=pA0l[g*8+t];     a0l[1]=pA0l[(8+g)*8+t];
            a0l[2]=pA0l[g*8+t+4];   a0l[3]=pA0l[(8+g)*8+t+4];
            a1h[0]=pA1h[g*8+t];     a1h[1]=pA1h[(8+g)*8+t];
            a1h[2]=pA1h[g*8+t+4];   a1h[3]=pA1h[(8+g)*8+t+4];
            a1l[0]=pA1l[g*8+t];     a1l[1]=pA1l[(8+g)*8+t];
            a1l[2]=pA1l[g*8+t+4];   a1l[3]=pA1l[(8+g)*8+t+4];
#pragma unroll
            for (int jj = 0; jj < 8; jj++) {
                const int j = ph*8 + jj;               // px tile 0..15
                const int Y = (j >> 2) + dy;           // 0..5
                const int X = (j & 3)*8 + dx + g;      // 0..33
                const unsigned* pBh = (const unsigned*)(PVh + (Y*34 + X)*16);
                const unsigned* pBl = (const unsigned*)(PVl + (Y*34 + X)*16);
                unsigned bh0 = pBh[t], bh1 = pBh[t+4];
                unsigned bl0 = pBl[t], bl1 = pBl[t+4];
                mma16816(d0[jj], a0h[0],a0h[1],a0h[2],a0h[3], bh0, bh1);  // hh
                mma16816(d0[jj], a0h[0],a0h[1],a0h[2],a0h[3], bl0, bl1);  // hl
                mma16816(d0[jj], a0l[0],a0l[1],a0l[2],a0l[3], bh0, bh1);  // lh
                mma16816(d1[jj], a1h[0],a1h[1],a1h[2],a1h[3], bh0, bh1);
                mma16816(d1[jj], a1h[0],a1h[1],a1h[2],a1h[3], bl0, bl1);
                mma16816(d1[jj], a1l[0],a1l[1],a1l[2],a1l[3], bh0, bh1);
            }
        }
    }

    // ---- epilogue: D frag (oc rows g, g+8; px cols 2t, 2t+1 per tile) ----
#pragma unroll
    for (int half = 0; half < 2; half++) {
        const int ocb = ob*32 + half*16;
        float (*dd)[4] = half ? d1 : d0;
        const int ocA = ocb + g, ocB = ocb + g + 8;
        float scA=0, bsA=0, scB=0, bsB=0;
        if (ocb < 64) {
            scA = bng[ocA] * rsqrtf(bnv[ocA] + BN_EPS);
            bsA = bnb[ocA] - bnm[ocA]*scA;
            scB = bng[ocB] * rsqrtf(bnv[ocB] + BN_EPS);
            bsB = bnb[ocB] - bnm[ocB]*scB;
        }
#pragma unroll
        for (int jj = 0; jj < 8; jj++) {
            const int j = ph*8 + jj;
            const int gy = ty0 + (j >> 2);
            const int lx = (j & 3)*8 + 2*t;
            if (ocb < 64) {
                float* oA = y1 + ((b*MID + ocA)*HH + gy)*WW + tx0 + lx;
                float* oB = y1 + ((b*MID + ocB)*HH + gy)*WW + tx0 + lx;
                oA[0] = fmaxf(dd[jj][0]*scA + bsA, 0.f);
                oA[1] = fmaxf(dd[jj][1]*scA + bsA, 0.f);
                oB[0] = fmaxf(dd[jj][2]*scB + bsB, 0.f);
                oB[1] = fmaxf(dd[jj][3]*scB + bsB, 0.f);
            } else {
                float* oA = z + ((b*MID + ocA - 64)*HH + gy)*WW + tx0 + lx;
                float* oB = z + ((b*MID + ocB - 64)*HH + gy)*WW + tx0 + lx;
                oA[0] = dd[jj][0];
                oA[1] = dd[jj][1];
                oB[0] = dd[jj][2];
                oB[1] = dd[jj][3];
            }
        }
    }
}

// =====================================================================
// conv_small: 64ch -> 64ch 3x3, optional add, bn, optional relu (fp32)
// =====================================================================
__global__ __launch_bounds__(256, 1) void conv_small_kernel(
    const float* __restrict__ in, const float* __restrict__ w, int w_oc_stride,
    const float* __restrict__ addp,
    const float* __restrict__ bng, const float* __restrict__ bnb,
    const float* __restrict__ bnm, const float* __restrict__ bnv,
    int relu, float* __restrict__ out)
{
    const int tx0 = blockIdx.x * 32, ty0 = blockIdx.y * 4, b = blockIdx.z;
    __shared__ float in_s[8][6][34];
    __shared__ float w_s[72][65];
    const int tid = threadIdx.x;
    const int og = tid >> 5;
    const int pg = tid & 31;
    const int lx = (pg & 7) * 4;
    const int ly = pg >> 3;

    float acc[8][4];
#pragma unroll
    for (int i = 0; i < 8; i++)
#pragma unroll
        for (int j = 0; j < 4; j++) acc[i][j] = 0.f;

    for (int ic0 = 0; ic0 < MID; ic0 += 8) {
        for (int i = tid; i < 8*6*34; i += 256) {
            int ic = i / 204, r = i % 204;
            int ry = r / 34, rx = r % 34;
            int gy = ty0 + ry - 1, gx = tx0 + rx - 1;
            float val = 0.f;
            if ((unsigned)gy < HH && (unsigned)gx < WW)
                val = in[((b*MID + ic0 + ic)*HH + gy)*WW + gx];
            in_s[ic][ry][rx] = val;
        }
        for (int e = tid; e < 64*72; e += 256) {
            int oc = e / 72, r = e % 72;
            int ic = r / 9, tap = r % 9;
            w_s[r][oc] = w[oc*w_oc_stride + (ic0 + ic)*9 + tap];
        }
        __syncthreads();
#pragma unroll
        for (int ic = 0; ic < 8; ic++) {
#pragma unroll
            for (int dy = 0; dy < 3; dy++) {
                float rin[6];
#pragma unroll
                for (int tt = 0; tt < 6; tt++) rin[tt] = in_s[ic][ly + dy][lx + tt];
#pragma unroll
                for (int dx = 0; dx < 3; dx++) {
                    float wr[8];
#pragma unroll
                    for (int i = 0; i < 8; i++) wr[i] = w_s[ic*9 + dy*3 + dx][og*8 + i];
#pragma unroll
                    for (int i = 0; i < 8; i++)
#pragma unroll
                        for (int j = 0; j < 4; j++)
                            acc[i][j] = fmaf(wr[i], rin[j + dx], acc[i][j]);
                }
            }
        }
        __syncthreads();
    }

    const int gy = ty0 + ly;
#pragma unroll
    for (int i = 0; i < 8; i++) {
        int oc = og*8 + i;
        float sc = bng[oc] * rsqrtf(bnv[oc] + BN_EPS);
        float bs = bnb[oc] - bnm[oc]*sc;
#pragma unroll
        for (int j = 0; j < 4; j++) {
            int idx = ((b*MID + oc)*HH + gy)*WW + tx0 + lx + j;
            float val = acc[i][j];
            if (addp) val += addp[idx];
            val = val*sc + bs;
            if (relu) val = fmaxf(val, 0.f);
            out[idx] = val;
        }
    }
}

// =====================================================================
// CCA kernels (unchanged from passing baseline)
// =====================================================================
__global__ __launch_bounds__(128) void proj_kernel(
    const float* __restrict__ in, const float* __restrict__ wq,
    const float* __restrict__ wk, const float* __restrict__ wv,
    float* __restrict__ q, float* __restrict__ k, float* __restrict__ v)
{
    __shared__ float swq[DQ*MID], swk[DQ*MID], swv[MID*MID];
    const int tid = threadIdx.x;
    for (int i = tid; i < DQ*MID; i += 128) { swq[i] = wq[i]; swk[i] = wk[i]; }
    for (int i = tid; i < MID*MID; i += 128) swv[i] = wv[i];
    __syncthreads();

    const int px = blockIdx.x*128 + tid;
    const int b = px / NPIX, hw = px % NPIX;
    float aq[DQ], ak[DQ], av[MID];
#pragma unroll
    for (int d = 0; d < DQ; d++) { aq[d] = 0.f; ak[d] = 0.f; }
#pragma unroll
    for (int d = 0; d < MID; d++) av[d] = 0.f;

    for (int c = 0; c < MID; c++) {
        float xv = in[(b*MID + c)*NPIX + hw];
#pragma unroll
        for (int d = 0; d < DQ; d++) { aq[d] += swq[d*MID + c]*xv; ak[d] += swk[d*MID + c]*xv; }
#pragma unroll
        for (int d = 0; d < MID; d++) av[d] += swv[d*MID + c]*xv;
    }
#pragma unroll
    for (int d = 0; d < DQ; d++) {
        q[(b*DQ + d)*NPIX + hw] = aq[d];
        k[(b*DQ + d)*NPIX + hw] = ak[d];
    }
#pragma unroll
    for (int d = 0; d < MID; d++) v[(b*MID + d)*NPIX + hw] = av[d];
}

__global__ __launch_bounds__(128) void energyH_kernel(
    const float* __restrict__ q, const float* __restrict__ k, float* __restrict__ att)
{
    const int b = blockIdx.x / WW, w = blockIdx.x % WW;
    __shared__ float qs[DQ][HH], ks[DQ][HH];
    const int tid = threadIdx.x;
    for (int i = tid; i < DQ*HH; i += 128) {
        int d = i / HH, h = i % HH;
        qs[d][h] = q[((b*DQ + d)*HH + h)*WW + w];
        ks[d][h] = k[((b*DQ + d)*HH + h)*WW + w];
    }
    __syncthreads();
    for (int i = tid; i < HH*HH; i += 128) {
        int h = i / HH, kk = i % HH;
        float e = 0.f;
#pragma unroll
        for (int d = 0; d < DQ; d++) e += qs[d][h]*ks[d][kk];
        att[((size_t)(b*HH + h)*WW + w)*192 + kk] = (kk == h) ? -INFINITY : e;
    }
}

__global__ __launch_bounds__(128) void energyW_kernel(
    const float* __restrict__ q, const float* __restrict__ k, float* __restrict__ att)
{
    const int b = blockIdx.x / HH, h = blockIdx.x % HH;
    __shared__ float qs[DQ][WW], ks[DQ][WW];
    const int tid = threadIdx.x;
    for (int i = tid; i < DQ*WW; i += 128) {
        int d = i / WW, w = i % WW;
        qs[d][w] = q[((b*DQ + d)*HH + h)*WW + w];
        ks[d][w] = k[((b*DQ + d)*HH + h)*WW + w];
    }
    __syncthreads();
    for (int i = tid; i < WW*WW; i += 128) {
        int w = i / WW, kk = i % WW;
        float e = 0.f;
#pragma unroll
        for (int d = 0; d < DQ; d++) e += qs[d][w]*ks[d][kk];
        att[((size_t)(b*HH + h)*WW + w)*192 + 96 + kk] = e;
    }
}

__global__ __launch_bounds__(256) void softmax_kernel(float* __restrict__ att)
{
    const int warp = threadIdx.x >> 5, lane = threadIdx.x & 31;
    const int px = blockIdx.x*8 + warp;
    float* p = att + (size_t)px*192;
    float vv[6];
#pragma unroll
    for (int i = 0; i < 6; i++) vv[i] = p[lane + 32*i];
    float mx = vv[0];
#pragma unroll
    for (int i = 1; i < 6; i++) mx = fmaxf(mx, vv[i]);
#pragma unroll
    for (int off = 16; off; off >>= 1) mx = fmaxf(mx, __shfl_xor_sync(0xffffffffu, mx, off));
    float s = 0.f;
#pragma unroll
    for (int i = 0; i < 6; i++) { vv[i] = expf(vv[i] - mx); s += vv[i]; }
#pragma unroll
    for (int off = 16; off; off >>= 1) s += __shfl_xor_sync(0xffffffffu, s, off);
    float inv = 1.f / s;
#pragma unroll
    for (int i = 0; i < 6; i++) p[lane + 32*i] = vv[i]*inv;
}

__global__ __launch_bounds__(256) void aggH_kernel(
    const float* __restrict__ att, const float* __restrict__ v, float* __restrict__ oH)
{
    const int b = blockIdx.x / WW, w = blockIdx.x % WW;
    __shared__ float vs[MID][97];
    __shared__ float as[HH][33];
    const int tid = threadIdx.x;
    for (int i = tid; i < MID*HH; i += 256) {
        int c = i / HH, kk = i % HH;
        vs[c][kk] = v[((b*MID + c)*HH + kk)*WW + w];
    }
    const int hbase = tid >> 4;
    const int cg = (tid & 15) * 4;
    float acc[4][6];
#pragma unroll
    for (int a = 0; a < 4; a++)
#pragma unroll
        for (int t = 0; t < 6; t++) acc[a][t] = 0.f;

    for (int k0 = 0; k0 < HH; k0 += 32) {
        __syncthreads();
        for (int i = tid; i < HH*32; i += 256) {
            int h = i >> 5, kk = i & 31;
            as[h][kk] = att[((size_t)(b*HH + h)*WW + w)*192 + k0 + kk];
        }
        __syncthreads();
#pragma unroll
        for (int kk = 0; kk < 32; kk++) {
            float ah[6], vl[4];
#pragma unroll
            for (int t = 0; t < 6; t++) ah[t] = as[hbase + 16*t][kk];
#pragma unroll
            for (int a = 0; a < 4; a++) vl[a] = vs[cg + a][k0 + kk];
#pragma unroll
            for (int a = 0; a < 4; a++)
#pragma unroll
                for (int t = 0; t < 6; t++) acc[a][t] = fmaf(vl[a], ah[t], acc[a][t]);
        }
    }
#pragma unroll
    for (int a = 0; a < 4; a++)
#pragma unroll
        for (int t = 0; t < 6; t++)
            oH[((b*MID + cg + a)*HH + hbase + 16*t)*WW + w] = acc[a][t];
}

__global__ __launch_bounds__(256) void aggW_kernel(
    const float* __restrict__ att, const float* __restrict__ v,
    const float* __restrict__ oH, const float* __restrict__ xin,
    const float* __restrict__ gamma, float* __restrict__ out)
{
    const int b = blockIdx.x / HH, h = blockIdx.x % HH;
    __shared__ float vs[MID][97];
    __shared__ float as[WW][33];
    const int tid = threadIdx.x;
    for (int i = tid; i < MID*WW; i += 256) {
        int c = i / WW, kk = i % WW;
        vs[c][kk] = v[((b*MID + c)*HH + h)*WW + kk];
    }
    const int wbase = tid >> 4;
    const int cg = (tid & 15) * 4;
    float acc[4][6];
#pragma unroll
    for (int a = 0; a < 4; a++)
#pragma unroll
        for (int t = 0; t < 6; t++) acc[a][t] = 0.f;

    for (int k0 = 0; k0 < WW; k0 += 32) {
        __syncthreads();
        for (int i = tid; i < WW*32; i += 256) {
            int w = i >> 5, kk = i & 31;
            as[w][kk] = att[((size_t)(b*HH + h)*WW + w)*192 + 96 + k0 + kk];
        }
        __syncthreads();
#pragma unroll
        for (int kk = 0; kk < 32; kk++) {
            float aw[6], vl[4];
#pragma unroll
            for (int t = 0; t < 6; t++) aw[t] = as[wbase + 16*t][kk];
#pragma unroll
            for (int a = 0; a < 4; a++) vl[a] = vs[cg + a][k0 + kk];
#pragma unroll
            for (int a = 0; a < 4; a++)
#pragma unroll
                for (int t = 0; t < 6; t++) acc[a][t] = fmaf(vl[a], aw[t], acc[a][t]);
        }
    }
    const float gm = gamma[0];
#pragma unroll
    for (int a = 0; a < 4; a++)
#pragma unroll
        for (int t = 0; t < 6; t++) {
            int idx = ((b*MID + cg + a)*HH + h)*WW + wbase + 16*t;
            out[idx] = gm*(oH[idx] + acc[a][t]) + xin[idx];
        }
}

// =====================================================================
// cls2 (1x1 conv 64->19) at 96x96 — commuted ahead of upsample
// =====================================================================
__global__ __launch_bounds__(256) void cls2_kernel(
    const float* __restrict__ t, const float* __restrict__ w2, float* __restrict__ sm)
{
    __shared__ float sw[NC*MID];
    const int tid = threadIdx.x;
    for (int i = tid; i < NC*MID; i += 256) sw[i] = w2[i];
    __syncthreads();
    const int px = blockIdx.x*256 + tid;
    const int b = px / NPIX, hw = px % NPIX;
    float acc[NC];
#pragma unroll
    for (int n = 0; n < NC; n++) acc[n] = 0.f;
    for (int c = 0; c < MID; c++) {
        float xv = t[(b*MID + c)*NPIX + hw];
#pragma unroll
        for (int n = 0; n < NC; n++) acc[n] += sw[n*MID + c]*xv;
    }
#pragma unroll
    for (int n = 0; n < NC; n++) sm[(b*NC + n)*NPIX + hw] = acc[n];
}

// =====================================================================
// bilinear upsample align_corners 96 -> 768
// =====================================================================
__global__ __launch_bounds__(256) void upsample_kernel(
    const float* __restrict__ sm, float* __restrict__ out)
{
    const int idx = blockIdx.x*256 + threadIdx.x;
    const int x  = idx % 768;
    const int y  = (idx / 768) % 768;
    const int bc = idx / (768*768);
    const float s = (float)(95.0 / 767.0);
    float py = (float)y * s, px = (float)x * s;
    int ly = (int)floorf(py), lx = (int)floorf(px);
    int hy = min(ly + 1, 95), hx = min(lx + 1, 95);
    float wy = py - (float)ly, wx = px - (float)lx;
    const float* p = sm + (size_t)bc * NPIX;
    float a = p[ly*96 + lx]*(1.f - wy) + p[hy*96 + lx]*wy;
    float b = p[ly*96 + hx]*(1.f - wy) + p[hy*96 + hx]*wy;
    out[idx] = a*(1.f - wx) + b*wx;
}

// =====================================================================
// launch
// =====================================================================
extern "C" void kernel_launch(void* const* d_in, const int* in_sizes, int n_in,
                              void* d_out, int out_size)
{
    const float* x      = (const float*)d_in[0];
    const float* w_in   = (const float*)d_in[1];
    const float* bin_g  = (const float*)d_in[2];
    const float* bin_b  = (const float*)d_in[3];
    const float* bin_m  = (const float*)d_in[4];
    const float* bin_v  = (const float*)d_in[5];
    const float* wq     = (const float*)d_in[6];
    const float* wk     = (const float*)d_in[7];
    const float* wv     = (const float*)d_in[8];
    const float* gamma  = (const float*)d_in[9];
    const float* w_out  = (const float*)d_in[10];
    const float* bo_g   = (const float*)d_in[11];
    const float* bo_b   = (const float*)d_in[12];
    const float* bo_m   = (const float*)d_in[13];
    const float* bo_v   = (const float*)d_in[14];
    const float* w_cls1 = (const float*)d_in[15];
    const float* bc_g   = (const float*)d_in[16];
    const float* bc_b   = (const float*)d_in[17];
    const float* bc_m   = (const float*)d_in[18];
    const float* bc_v   = (const float*)d_in[19];
    const float* w_cls2 = (const float*)d_in[20];

    float *y1, *z, *fa, *fb, *q, *k, *v, *att, *oH, *sm;
    __nv_bfloat16 *wh, *wl;
    cudaGetSymbolAddress((void**)&y1, g_y1);
    cudaGetSymbolAddress((void**)&z,  g_z);
    cudaGetSymbolAddress((void**)&fa, g_fa);
    cudaGetSymbolAddress((void**)&fb, g_fb);
    cudaGetSymbolAddress((void**)&q,  g_q);
    cudaGetSymbolAddress((void**)&k,  g_k);
    cudaGetSymbolAddress((void**)&v,  g_v);
    cudaGetSymbolAddress((void**)&att, g_att);
    cudaGetSymbolAddress((void**)&oH, g_oH);
    cudaGetSymbolAddress((void**)&sm, g_small);
    cudaGetSymbolAddress((void**)&wh, g_wh);
    cudaGetSymbolAddress((void**)&wl, g_wl);

    // idempotent, non-enqueuing, called every launch (no static guards allowed)
    cudaFuncSetAttribute(conv_big_mma,
                         cudaFuncAttributeMaxDynamicSharedMemorySize, SMEM_DYN);

    dim3 cgrid(3, 24, BB);

    // Stage 0: weight reorder + bf16 hi/lo split (deterministic each call)
    weight_prep_kernel<<<WPREP_ELEMS/256, 256>>>(w_in, w_cls1, wh, wl);

    // Stage 1: fused conv_in (bn+relu) + cls1 x-slice partials — tensor cores
    conv_big_mma<<<cgrid, 256, SMEM_DYN>>>(x, wh, wl,
                                           bin_g, bin_b, bin_m, bin_v, y1, z);

    // Stage 2: 2x criss-cross attention (r0: y1->fa, r1: fa->fb; final in fb)
    const float* cca_in = y1;
    float* cca_out = fa;
    for (int r = 0; r < 2; r++) {
        proj_kernel   <<<BB*NPIX/128, 128>>>(cca_in, wq, wk, wv, q, k, v);
        energyH_kernel<<<BB*WW, 128>>>(q, k, att);
        energyW_kernel<<<BB*HH, 128>>>(q, k, att);
        softmax_kernel<<<BB*NPIX/8, 256>>>(att);
        aggH_kernel   <<<BB*WW, 256>>>(att, v, oH);
        aggW_kernel   <<<BB*HH, 256>>>(att, v, oH, cca_in, gamma, cca_out);
        cca_in = cca_out;
        cca_out = fb;
    }

    // Stage 3: conv_out (bn+relu)
    conv_small_kernel<<<cgrid, 256>>>(fb, w_out, 64*9, (const float*)0,
                                      bo_g, bo_b, bo_m, bo_v, 1, y1);

    // Stage 4: cls1 out-slice conv + stashed x-part + bn_cls (no relu)
    conv_small_kernel<<<cgrid, 256>>>(y1, w_cls1 + 2048*9, 2112*9, z,
                                      bc_g, bc_b, bc_m, bc_v, 0, fa);

    // Stage 5: 1x1 conv 64->19 at 96x96
    cls2_kernel<<<BB*NPIX/256, 256>>>(fa, w_cls2, sm);

    // Stage 6: bilinear x8 upsample
    upsample_kernel<<<(BB*NC*768*768)/256, 256>>>(sm, (float*)d_out);
}